// round 5
// baseline (speedup 1.0000x reference)
#include <cuda_runtime.h>
#include <cuda_bf16.h>
#include <math.h>
#include <stdint.h>

// Problem constants
#define B_   2
#define T_   2048
#define D_   1024
#define NH_  16
#define DH_  64
#define RTOT (B_*T_)          // 4096 rows
#define K_   D_               // GEMM K dim

// ---------------------------------------------------------------------------
// Scratch (no cudaMalloc allowed)
// Q,K,V,ctx row-major (b,t, h*64+dh) = [4096][1024] fp32
// ---------------------------------------------------------------------------
__device__ float g_Q[RTOT*D_];
__device__ float g_K[RTOT*D_];
__device__ float g_V[RTOT*D_];
__device__ float g_ctx[RTOT*D_];
__device__ __nv_bfloat16 g_Xhi[RTOT*D_], g_Xlo[RTOT*D_];
__device__ __nv_bfloat16 g_Chi[RTOT*D_], g_Clo[RTOT*D_];
// transposed weights: [mat 0..3 = Wq,Wk,Wv,Wo][N][K] bf16 (K-major rows)
__device__ __nv_bfloat16 g_WThi[4][D_*D_];
__device__ __nv_bfloat16 g_WTlo[4][D_*D_];

// ---------------------------------------------------------------------------
// PTX helpers (standard PTX only — no sm_103a-gated instructions)
// ---------------------------------------------------------------------------
__device__ __forceinline__ uint32_t smem_u32(const void* p) {
    uint32_t a;
    asm("{ .reg .u64 t; cvta.to.shared.u64 t, %1; cvt.u32.u64 %0, t; }"
        : "=r"(a) : "l"(p));
    return a;
}

#define CP_ASYNC16(dst, src) \
    asm volatile("cp.async.cg.shared.global [%0], [%1], 16;" \
                 :: "r"(dst), "l"(src))
#define CP_COMMIT() asm volatile("cp.async.commit_group;" ::: "memory")
#define CP_WAIT(n)  asm volatile("cp.async.wait_group %0;" :: "n"(n) : "memory")

__device__ __forceinline__ void ldsm4(uint32_t* r, uint32_t addr) {
    asm volatile("ldmatrix.sync.aligned.m8n8.x4.shared.b16 {%0,%1,%2,%3}, [%4];"
                 : "=r"(r[0]), "=r"(r[1]), "=r"(r[2]), "=r"(r[3]) : "r"(addr));
}

__device__ __forceinline__ void mma_bf16(float* d, const uint32_t* a,
                                         const uint32_t* b) {
    asm volatile(
        "mma.sync.aligned.m16n8k16.row.col.f32.bf16.bf16.f32 "
        "{%0,%1,%2,%3}, {%4,%5,%6,%7}, {%8,%9}, {%0,%1,%2,%3};"
        : "+f"(d[0]), "+f"(d[1]), "+f"(d[2]), "+f"(d[3])
        : "r"(a[0]), "r"(a[1]), "r"(a[2]), "r"(a[3]), "r"(b[0]), "r"(b[1]));
}

// ---------------------------------------------------------------------------
// Precision-split helpers / kernels
// ---------------------------------------------------------------------------
__global__ __launch_bounds__(256) void split_kernel(const float* __restrict__ srcParam,
                                                    int mode)
{
    const float* src = mode ? g_ctx : srcParam;
    __nv_bfloat16* hi = mode ? g_Chi : g_Xhi;
    __nv_bfloat16* lo = mode ? g_Clo : g_Xlo;

    int i = (blockIdx.x * 256 + threadIdx.x) * 4;
    float4 v = *(const float4*)(src + i);
    float vv[4] = {v.x, v.y, v.z, v.w};
    __nv_bfloat16 h[4], l[4];
#pragma unroll
    for (int j = 0; j < 4; j++) {
        h[j] = __float2bfloat16(vv[j]);
        l[j] = __float2bfloat16(vv[j] - __bfloat162float(h[j]));
    }
    *(__nv_bfloat162*)(hi + i)     = __nv_bfloat162(h[0], h[1]);
    *(__nv_bfloat162*)(hi + i + 2) = __nv_bfloat162(h[2], h[3]);
    *(__nv_bfloat162*)(lo + i)     = __nv_bfloat162(l[0], l[1]);
    *(__nv_bfloat162*)(lo + i + 2) = __nv_bfloat162(l[2], l[3]);
}

// Transpose + split weights: W [K][N] fp32 -> [N][K] bf16 hi/lo
__global__ __launch_bounds__(256) void wtrans_kernel(const float* __restrict__ Wq,
                                                     const float* __restrict__ Wk,
                                                     const float* __restrict__ Wv,
                                                     const float* __restrict__ Wo)
{
    int z = blockIdx.z;
    const float* W = (z == 0) ? Wq : (z == 1) ? Wk : (z == 2) ? Wv : Wo;
    __nv_bfloat16* Bhi = g_WThi[z];
    __nv_bfloat16* Blo = g_WTlo[z];

    __shared__ float t[32][33];
    int n0 = blockIdx.x * 32, k0 = blockIdx.y * 32;
    for (int i = threadIdx.y; i < 32; i += 8)
        t[i][threadIdx.x] = W[(size_t)(k0 + i) * D_ + n0 + threadIdx.x];
    __syncthreads();
    for (int i = threadIdx.y; i < 32; i += 8) {
        float v = t[threadIdx.x][i];           // = W[k0+tx][n0+i]
        __nv_bfloat16 h = __float2bfloat16(v);
        float r = v - __bfloat162float(h);
        Bhi[(size_t)(n0 + i) * D_ + k0 + threadIdx.x] = h;
        Blo[(size_t)(n0 + i) * D_ + k0 + threadIdx.x] = __float2bfloat16(r);
    }
}

// ---------------------------------------------------------------------------
// Tensor-core GEMM via mma.sync (bf16 x3 split precision).
// C[4096][1024] = A @ B^T.  Tile 128(M) x 128(N), BK=32, 8 warps of 64x32.
// Double-buffered cp.async pipeline; smem rows padded to 80B (conflict-free
// ldmatrix: row starts hit bank groups {0,20,8,28,16,4,24,12}).
// mode 0: A = X(hi/lo), B = W[z], C = Q/K/V per blockIdx.z
// mode 1: A = ctx(hi/lo), B = W[3], C = outParam
// ---------------------------------------------------------------------------
#define SROWB   80                  // padded row stride in bytes (32 bf16 + 8 pad)
#define MAT_B   (128*SROWB)         // 10240 bytes per matrix tile
#define STAGE_B (4*MAT_B)           // Ahi, Alo, Bhi, Blo
#define GEMM_SMEM (2*STAGE_B)       // 81920
#define KITER   (K_/32)             // 32

__global__ __launch_bounds__(256, 2) void gemm_kernel(int mode, float* outParam)
{
    extern __shared__ char sm[];
    const uint32_t sb = smem_u32(sm);
    const int tid  = threadIdx.x;
    const int wid  = tid >> 5;
    const int lane = tid & 31;
    const int wm   = wid & 1;        // 2 warp-rows   (64 rows each)
    const int wn   = wid >> 1;       // 4 warp-cols   (32 cols each)

    const __nv_bfloat16 *Ahi, *Alo, *Bhi, *Blo;
    float* C;
    if (mode == 0) {
        Ahi = g_Xhi; Alo = g_Xlo;
        int z = blockIdx.z;
        Bhi = g_WThi[z]; Blo = g_WTlo[z];
        C = (z == 0) ? g_Q : (z == 1) ? g_K : g_V;
    } else {
        Ahi = g_Chi; Alo = g_Clo;
        Bhi = g_WThi[3]; Blo = g_WTlo[3];
        C = outParam;
    }

    const int rowBase = blockIdx.y * 128;
    const int colBase = blockIdx.x * 128;

    float acc[4][4][4];
#pragma unroll
    for (int i = 0; i < 4; i++)
#pragma unroll
        for (int j = 0; j < 4; j++)
#pragma unroll
            for (int e = 0; e < 4; e++) acc[i][j][e] = 0.0f;

    // ---- stage loader: 512 x 16B chunks per matrix, 4 matrices ----
    auto load_stage = [&](int st, int k0) {
        uint32_t s0 = sb + st * STAGE_B;
#pragma unroll
        for (int i = 0; i < 2; i++) {
            int c  = tid + i * 256;          // 0..511
            int r  = c >> 2;
            int c4 = c & 3;
            uint32_t soff = r * SROWB + c4 * 16;
            size_t ga = (size_t)(rowBase + r) * K_ + k0 + c4 * 8;
            size_t gb = (size_t)(colBase + r) * K_ + k0 + c4 * 8;
            CP_ASYNC16(s0 + soff,             Ahi + ga);
            CP_ASYNC16(s0 + MAT_B + soff,     Alo + ga);
            CP_ASYNC16(s0 + 2 * MAT_B + soff, Bhi + gb);
            CP_ASYNC16(s0 + 3 * MAT_B + soff, Blo + gb);
        }
    };

    // ---- compute one 32-wide K stage ----
    auto compute_stage = [&](int st) {
        uint32_t pAh = sb + st * STAGE_B;
        uint32_t pAl = pAh + MAT_B;
        uint32_t pBh = pAh + 2 * MAT_B;
        uint32_t pBl = pAh + 3 * MAT_B;
#pragma unroll
        for (int ks = 0; ks < 2; ks++) {
            // A fragments: 4 m-blocks of 16, hi & lo
            uint32_t ah[4][4], al[4][4];
            const int akc = ks * 16 + (lane >> 4) * 8;
#pragma unroll
            for (int mb = 0; mb < 4; mb++) {
                uint32_t off = (uint32_t)(wm * 64 + mb * 16 + (lane & 15)) * SROWB
                             + akc * 2;
                ldsm4(ah[mb], pAh + off);
                ldsm4(al[mb], pAl + off);
            }
            // B fragments: 4 n-blocks of 8 (two x4 ldmatrix each for hi/lo)
            uint32_t bh[4][2], bl[4][2];
            const int brow = (lane & 7) + ((lane >> 4) & 1) * 8;
            const int bkc  = ks * 16 + ((lane >> 3) & 1) * 8;
#pragma unroll
            for (int nb2 = 0; nb2 < 2; nb2++) {
                uint32_t off = (uint32_t)(wn * 32 + nb2 * 16 + brow) * SROWB
                             + bkc * 2;
                uint32_t t0[4], t1[4];
                ldsm4(t0, pBh + off);
                ldsm4(t1, pBl + off);
                bh[nb2*2][0] = t0[0]; bh[nb2*2][1] = t0[1];
                bh[nb2*2+1][0] = t0[2]; bh[nb2*2+1][1] = t0[3];
                bl[nb2*2][0] = t1[0]; bl[nb2*2][1] = t1[1];
                bl[nb2*2+1][0] = t1[2]; bl[nb2*2+1][1] = t1[3];
            }
            // 3-pass split-precision MMA
#pragma unroll
            for (int mb = 0; mb < 4; mb++)
#pragma unroll
                for (int nb = 0; nb < 4; nb++) {
                    mma_bf16(acc[mb][nb], ah[mb], bh[nb]);
                    mma_bf16(acc[mb][nb], ah[mb], bl[nb]);
                    mma_bf16(acc[mb][nb], al[mb], bh[nb]);
                }
        }
    };

    // ---- pipeline ----
    load_stage(0, 0);
    CP_COMMIT();
    for (int it = 0; it < KITER; it++) {
        if (it + 1 < KITER) {
            load_stage((it + 1) & 1, (it + 1) * 32);
            CP_COMMIT();
            CP_WAIT(1);
        } else {
            CP_WAIT(0);
        }
        __syncthreads();
        compute_stage(it & 1);
        __syncthreads();
    }

    // ---- epilogue ----
#pragma unroll
    for (int mb = 0; mb < 4; mb++) {
        int r0 = rowBase + wm * 64 + mb * 16 + (lane >> 2);
#pragma unroll
        for (int nb = 0; nb < 4; nb++) {
            int cc = colBase + wn * 32 + nb * 8 + (lane & 3) * 2;
            *(float2*)(C + (size_t)r0 * D_ + cc) =
                make_float2(acc[mb][nb][0], acc[mb][nb][1]);
            *(float2*)(C + (size_t)(r0 + 8) * D_ + cc) =
                make_float2(acc[mb][nb][2], acc[mb][nb][3]);
        }
    }
}

// ---------------------------------------------------------------------------
// Flash attention (causal), SIMT fp32. QKV row-major [4096][1024], head off h*64.
// ---------------------------------------------------------------------------
#define PADK 68
#define ATTN_SMEM_FLOATS (64*64 + 64*PADK + 64*64)
#define ATTN_SMEM_BYTES  (ATTN_SMEM_FLOATS * 4)

__global__ __launch_bounds__(256) void attn_kernel()
{
    extern __shared__ float smf[];
    float* sQ  = smf;                   // [64][64], pre-scaled
    float* sKP = smf + 64 * 64;         // [64][PADK]  K tile, then P tile
    float* sV  = sKP + 64 * PADK;       // [64][64]

    const int qt = (int)gridDim.x - 1 - (int)blockIdx.x;
    const int h  = blockIdx.y;
    const int b  = blockIdx.z;

    const int tid = threadIdx.x;
    const int w   = tid >> 5;
    const int l   = tid & 31;
    const int i0  = w * 8;

    const float* Qg = g_Q + (size_t)(b * T_ + qt * 64) * D_ + h * DH_;
    const float* Kb = g_K + (size_t)(b * T_) * D_ + h * DH_;
    const float* Vb = g_V + (size_t)(b * T_) * D_ + h * DH_;

    const float scale = 0.125f;

    for (int idx = tid; idx < 64 * 16; idx += 256) {
        int row = idx >> 4;
        int c4  = (idx & 15) << 2;
        float4 v = *(const float4*)(Qg + (size_t)row * D_ + c4);
        v.x *= scale; v.y *= scale; v.z *= scale; v.w *= scale;
        *(float4*)(sQ + row * 64 + c4) = v;
    }

    float mrow[8], lsum[8], o0[8], o1[8];
#pragma unroll
    for (int ii = 0; ii < 8; ii++) {
        mrow[ii] = -INFINITY; lsum[ii] = 0.0f; o0[ii] = 0.0f; o1[ii] = 0.0f;
    }

    __syncthreads();

    for (int kt = 0; kt <= qt; kt++) {
        const float* Kt = Kb + (size_t)kt * 64 * D_;
        const float* Vt = Vb + (size_t)kt * 64 * D_;
        for (int idx = tid; idx < 64 * 16; idx += 256) {
            int row = idx >> 4;
            int c4  = (idx & 15) << 2;
            *(float4*)(sKP + row * PADK + c4) = *(const float4*)(Kt + (size_t)row * D_ + c4);
            *(float4*)(sV  + row * 64   + c4) = *(const float4*)(Vt + (size_t)row * D_ + c4);
        }
        __syncthreads();

        float s0[8], s1[8];
#pragma unroll
        for (int ii = 0; ii < 8; ii++) { s0[ii] = 0.0f; s1[ii] = 0.0f; }

#pragma unroll 4
        for (int d = 0; d < 64; d += 4) {
            float4 k0v = *(float4*)(sKP + l * PADK + d);
            float4 k1v = *(float4*)(sKP + (l + 32) * PADK + d);
#pragma unroll
            for (int ii = 0; ii < 8; ii++) {
                float4 qv = *(float4*)(sQ + (i0 + ii) * 64 + d);
                s0[ii] += qv.x * k0v.x + qv.y * k0v.y + qv.z * k0v.z + qv.w * k0v.w;
                s1[ii] += qv.x * k1v.x + qv.y * k1v.y + qv.z * k1v.z + qv.w * k1v.w;
            }
        }

        if (kt == qt) {
#pragma unroll
            for (int ii = 0; ii < 8; ii++) {
                if (l      > i0 + ii) s0[ii] = -INFINITY;
                if (l + 32 > i0 + ii) s1[ii] = -INFINITY;
            }
        }

        __syncthreads();

#pragma unroll
        for (int ii = 0; ii < 8; ii++) {
            float mt = fmaxf(s0[ii], s1[ii]);
#pragma unroll
            for (int off = 16; off; off >>= 1)
                mt = fmaxf(mt, __shfl_xor_sync(0xffffffffu, mt, off));
            float mnew = fmaxf(mrow[ii], mt);
            float p0 = __expf(s0[ii] - mnew);
            float p1 = __expf(s1[ii] - mnew);
            float corr = __expf(mrow[ii] - mnew);
            float rs = p0 + p1;
#pragma unroll
            for (int off = 16; off; off >>= 1)
                rs += __shfl_xor_sync(0xffffffffu, rs, off);
            lsum[ii] = lsum[ii] * corr + rs;
            mrow[ii] = mnew;
            o0[ii] *= corr;
            o1[ii] *= corr;
            sKP[(i0 + ii) * PADK + l]      = p0;
            sKP[(i0 + ii) * PADK + l + 32] = p1;
        }

        __syncthreads();

#pragma unroll 4
        for (int j = 0; j < 64; j += 4) {
            float4 pv[8];
#pragma unroll
            for (int ii = 0; ii < 8; ii++)
                pv[ii] = *(float4*)(sKP + (i0 + ii) * PADK + j);
#pragma unroll
            for (int jj = 0; jj < 4; jj++) {
                float v0 = sV[(j + jj) * 64 + l];
                float v1 = sV[(j + jj) * 64 + l + 32];
#pragma unroll
                for (int ii = 0; ii < 8; ii++) {
                    float p = (jj == 0) ? pv[ii].x : (jj == 1) ? pv[ii].y
                            : (jj == 2) ? pv[ii].z : pv[ii].w;
                    o0[ii] += p * v0;
                    o1[ii] += p * v1;
                }
            }
        }

        __syncthreads();
    }

    float* ctx = g_ctx + (size_t)(b * T_ + qt * 64) * D_ + h * DH_;
#pragma unroll
    for (int ii = 0; ii < 8; ii++) {
        float inv = 1.0f / lsum[ii];
        ctx[(size_t)(i0 + ii) * D_ + l]      = o0[ii] * inv;
        ctx[(size_t)(i0 + ii) * D_ + l + 32] = o1[ii] * inv;
    }
}

// ---------------------------------------------------------------------------

extern "C" void kernel_launch(void* const* d_in, const int* in_sizes, int n_in,
                              void* d_out, int out_size)
{
    const float* x  = (const float*)d_in[0];
    const float* Wq = (const float*)d_in[1];
    const float* Wk = (const float*)d_in[2];
    const float* Wv = (const float*)d_in[3];
    const float* Wo = (const float*)d_in[4];
    float* out = (float*)d_out;

    cudaFuncSetAttribute(gemm_kernel, cudaFuncAttributeMaxDynamicSharedMemorySize,
                         GEMM_SMEM);
    cudaFuncSetAttribute(attn_kernel, cudaFuncAttributeMaxDynamicSharedMemorySize,
                         ATTN_SMEM_BYTES);

    // Split x into bf16 hi/lo; transpose+split all 4 weight matrices
    split_kernel<<<RTOT * D_ / 1024, 256>>>(x, 0);
    wtrans_kernel<<<dim3(32, 32, 4), dim3(32, 8)>>>(Wq, Wk, Wv, Wo);

    // QKV projections on tensor cores (z = q/k/v)
    gemm_kernel<<<dim3(D_ / 128, RTOT / 128, 3), 256, GEMM_SMEM>>>(0, nullptr);

    // Causal flash attention (SIMT fp32)
    attn_kernel<<<dim3(T_ / 64, NH_, B_), 256, ATTN_SMEM_BYTES>>>();

    // Split ctx, then output projection on tensor cores
    split_kernel<<<RTOT * D_ / 1024, 256>>>(nullptr, 1);
    gemm_kernel<<<dim3(D_ / 128, RTOT / 128, 1), 256, GEMM_SMEM>>>(1, out);
}

// round 6
// speedup vs baseline: 1.8482x; 1.8482x over previous
#include <cuda_runtime.h>
#include <cuda_bf16.h>
#include <math.h>
#include <stdint.h>

// Problem constants
#define B_   2
#define T_   2048
#define D_   1024
#define NH_  16
#define DH_  64
#define RTOT (B_*T_)          // 4096 rows
#define K_   D_               // GEMM K dim

// ---------------------------------------------------------------------------
// Scratch (no cudaMalloc allowed). All activation tensors as bf16 hi/lo splits.
// Layout: row-major [4096][1024], col = h*64 + dh.
// ---------------------------------------------------------------------------
__device__ __nv_bfloat16 g_Xhi[RTOT*D_], g_Xlo[RTOT*D_];
__device__ __nv_bfloat16 g_Qhi[RTOT*D_], g_Qlo[RTOT*D_];   // Q pre-scaled by 1/8
__device__ __nv_bfloat16 g_Khi[RTOT*D_], g_Klo[RTOT*D_];
__device__ __nv_bfloat16 g_Vhi[RTOT*D_], g_Vlo[RTOT*D_];
__device__ __nv_bfloat16 g_Chi[RTOT*D_], g_Clo[RTOT*D_];
// transposed weights: [mat 0..3 = Wq,Wk,Wv,Wo][N][K] bf16 (K-major rows)
__device__ __nv_bfloat16 g_WThi[4][D_*D_];
__device__ __nv_bfloat16 g_WTlo[4][D_*D_];

// ---------------------------------------------------------------------------
// PTX helpers (standard PTX only)
// ---------------------------------------------------------------------------
__device__ __forceinline__ uint32_t smem_u32(const void* p) {
    uint32_t a;
    asm("{ .reg .u64 t; cvta.to.shared.u64 t, %1; cvt.u32.u64 %0, t; }"
        : "=r"(a) : "l"(p));
    return a;
}

#define CP_ASYNC16(dst, src) \
    asm volatile("cp.async.cg.shared.global [%0], [%1], 16;" \
                 :: "r"(dst), "l"(src))
#define CP_COMMIT() asm volatile("cp.async.commit_group;" ::: "memory")
#define CP_WAIT(n)  asm volatile("cp.async.wait_group %0;" :: "n"(n) : "memory")

__device__ __forceinline__ void ldsm4(uint32_t* r, uint32_t addr) {
    asm volatile("ldmatrix.sync.aligned.m8n8.x4.shared.b16 {%0,%1,%2,%3}, [%4];"
                 : "=r"(r[0]), "=r"(r[1]), "=r"(r[2]), "=r"(r[3]) : "r"(addr));
}
__device__ __forceinline__ void ldsm4t(uint32_t* r, uint32_t addr) {
    asm volatile("ldmatrix.sync.aligned.m8n8.x4.trans.shared.b16 {%0,%1,%2,%3}, [%4];"
                 : "=r"(r[0]), "=r"(r[1]), "=r"(r[2]), "=r"(r[3]) : "r"(addr));
}

__device__ __forceinline__ void mma_bf16(float* d, const uint32_t* a,
                                         const uint32_t* b) {
    asm volatile(
        "mma.sync.aligned.m16n8k16.row.col.f32.bf16.bf16.f32 "
        "{%0,%1,%2,%3}, {%4,%5,%6,%7}, {%8,%9}, {%0,%1,%2,%3};"
        : "+f"(d[0]), "+f"(d[1]), "+f"(d[2]), "+f"(d[3])
        : "r"(a[0]), "r"(a[1]), "r"(a[2]), "r"(a[3]), "r"(b[0]), "r"(b[1]));
}

// pack two fp32 -> bf16x2 (a -> low half, b -> high half), round-to-nearest
__device__ __forceinline__ uint32_t pack_bf16(float a, float b) {
    uint32_t r;
    asm("cvt.rn.bf16x2.f32 %0, %1, %2;" : "=r"(r) : "f"(b), "f"(a));
    return r;
}

// hi/lo split of a float pair; writes packed hi and lo words
__device__ __forceinline__ void split_pair(float a, float b,
                                           uint32_t& H, uint32_t& L) {
    H = pack_bf16(a, b);
    float la = a - __uint_as_float(H << 16);
    float lb = b - __uint_as_float(H & 0xffff0000u);
    L = pack_bf16(la, lb);
}

// ---------------------------------------------------------------------------
// Split x into bf16 hi/lo
// ---------------------------------------------------------------------------
__global__ __launch_bounds__(256) void split_kernel(const float* __restrict__ src)
{
    int i = (blockIdx.x * 256 + threadIdx.x) * 4;
    float4 v = *(const float4*)(src + i);
    uint32_t H0, L0, H1, L1;
    split_pair(v.x, v.y, H0, L0);
    split_pair(v.z, v.w, H1, L1);
    *(uint32_t*)(g_Xhi + i)     = H0;
    *(uint32_t*)(g_Xhi + i + 2) = H1;
    *(uint32_t*)(g_Xlo + i)     = L0;
    *(uint32_t*)(g_Xlo + i + 2) = L1;
}

// Transpose + split weights: W [K][N] fp32 -> [N][K] bf16 hi/lo
__global__ __launch_bounds__(256) void wtrans_kernel(const float* __restrict__ Wq,
                                                     const float* __restrict__ Wk,
                                                     const float* __restrict__ Wv,
                                                     const float* __restrict__ Wo)
{
    int z = blockIdx.z;
    const float* W = (z == 0) ? Wq : (z == 1) ? Wk : (z == 2) ? Wv : Wo;
    __nv_bfloat16* Bhi = g_WThi[z];
    __nv_bfloat16* Blo = g_WTlo[z];

    __shared__ float t[32][33];
    int n0 = blockIdx.x * 32, k0 = blockIdx.y * 32;
    for (int i = threadIdx.y; i < 32; i += 8)
        t[i][threadIdx.x] = W[(size_t)(k0 + i) * D_ + n0 + threadIdx.x];
    __syncthreads();
    for (int i = threadIdx.y; i < 32; i += 8) {
        float v = t[threadIdx.x][i];           // = W[k0+tx][n0+i]
        __nv_bfloat16 h = __float2bfloat16(v);
        float r = v - __bfloat162float(h);
        Bhi[(size_t)(n0 + i) * D_ + k0 + threadIdx.x] = h;
        Blo[(size_t)(n0 + i) * D_ + k0 + threadIdx.x] = __float2bfloat16(r);
    }
}

// ---------------------------------------------------------------------------
// Tensor-core GEMM via mma.sync (bf16 x3 split precision).
// C[4096][1024] = A @ B^T.  Tile 128(M) x 128(N), BK=32, 8 warps of 64x32.
// mode 0: A = X(hi/lo), B = W[z], C -> bf16 hi/lo Q(scaled 1/8)/K/V per z
// mode 1: A = ctx(hi/lo), B = W[3], C -> fp32 outParam
// ---------------------------------------------------------------------------
#define SROWB   80                  // padded row stride in bytes
#define MAT_B   (128*SROWB)
#define STAGE_B (4*MAT_B)
#define GEMM_SMEM (2*STAGE_B)       // 81920
#define KITER   (K_/32)             // 32

__global__ __launch_bounds__(256, 2) void gemm_kernel(int mode, float* outParam)
{
    extern __shared__ char sm[];
    const uint32_t sb = smem_u32(sm);
    const int tid  = threadIdx.x;
    const int wid  = tid >> 5;
    const int lane = tid & 31;
    const int wm   = wid & 1;
    const int wn   = wid >> 1;

    const __nv_bfloat16 *Ahi, *Alo, *Bhi, *Blo;
    __nv_bfloat16 *Chi = nullptr, *Clo = nullptr;
    float scale = 1.0f;
    if (mode == 0) {
        Ahi = g_Xhi; Alo = g_Xlo;
        int z = blockIdx.z;
        Bhi = g_WThi[z]; Blo = g_WTlo[z];
        if (z == 0)      { Chi = g_Qhi; Clo = g_Qlo; scale = 0.125f; }
        else if (z == 1) { Chi = g_Khi; Clo = g_Klo; }
        else             { Chi = g_Vhi; Clo = g_Vlo; }
    } else {
        Ahi = g_Chi; Alo = g_Clo;
        Bhi = g_WThi[3]; Blo = g_WTlo[3];
    }

    const int rowBase = blockIdx.y * 128;
    const int colBase = blockIdx.x * 128;

    float acc[4][4][4];
#pragma unroll
    for (int i = 0; i < 4; i++)
#pragma unroll
        for (int j = 0; j < 4; j++)
#pragma unroll
            for (int e = 0; e < 4; e++) acc[i][j][e] = 0.0f;

    auto load_stage = [&](int st, int k0) {
        uint32_t s0 = sb + st * STAGE_B;
#pragma unroll
        for (int i = 0; i < 2; i++) {
            int c  = tid + i * 256;
            int r  = c >> 2;
            int c4 = c & 3;
            uint32_t soff = r * SROWB + c4 * 16;
            size_t ga = (size_t)(rowBase + r) * K_ + k0 + c4 * 8;
            size_t gb = (size_t)(colBase + r) * K_ + k0 + c4 * 8;
            CP_ASYNC16(s0 + soff,             Ahi + ga);
            CP_ASYNC16(s0 + MAT_B + soff,     Alo + ga);
            CP_ASYNC16(s0 + 2 * MAT_B + soff, Bhi + gb);
            CP_ASYNC16(s0 + 3 * MAT_B + soff, Blo + gb);
        }
    };

    auto compute_stage = [&](int st) {
        uint32_t pAh = sb + st * STAGE_B;
        uint32_t pAl = pAh + MAT_B;
        uint32_t pBh = pAh + 2 * MAT_B;
        uint32_t pBl = pAh + 3 * MAT_B;
#pragma unroll
        for (int ks = 0; ks < 2; ks++) {
            uint32_t ah[4][4], al[4][4];
            const int akc = ks * 16 + (lane >> 4) * 8;
#pragma unroll
            for (int mb = 0; mb < 4; mb++) {
                uint32_t off = (uint32_t)(wm * 64 + mb * 16 + (lane & 15)) * SROWB
                             + akc * 2;
                ldsm4(ah[mb], pAh + off);
                ldsm4(al[mb], pAl + off);
            }
            uint32_t bh[4][2], bl[4][2];
            const int brow = (lane & 7) + ((lane >> 4) & 1) * 8;
            const int bkc  = ks * 16 + ((lane >> 3) & 1) * 8;
#pragma unroll
            for (int nb2 = 0; nb2 < 2; nb2++) {
                uint32_t off = (uint32_t)(wn * 32 + nb2 * 16 + brow) * SROWB
                             + bkc * 2;
                uint32_t t0[4], t1[4];
                ldsm4(t0, pBh + off);
                ldsm4(t1, pBl + off);
                bh[nb2*2][0] = t0[0]; bh[nb2*2][1] = t0[1];
                bh[nb2*2+1][0] = t0[2]; bh[nb2*2+1][1] = t0[3];
                bl[nb2*2][0] = t1[0]; bl[nb2*2][1] = t1[1];
                bl[nb2*2+1][0] = t1[2]; bl[nb2*2+1][1] = t1[3];
            }
#pragma unroll
            for (int mb = 0; mb < 4; mb++)
#pragma unroll
                for (int nb = 0; nb < 4; nb++) {
                    mma_bf16(acc[mb][nb], ah[mb], bh[nb]);
                    mma_bf16(acc[mb][nb], ah[mb], bl[nb]);
                    mma_bf16(acc[mb][nb], al[mb], bh[nb]);
                }
        }
    };

    load_stage(0, 0);
    CP_COMMIT();
    for (int it = 0; it < KITER; it++) {
        if (it + 1 < KITER) {
            load_stage((it + 1) & 1, (it + 1) * 32);
            CP_COMMIT();
            CP_WAIT(1);
        } else {
            CP_WAIT(0);
        }
        __syncthreads();
        compute_stage(it & 1);
        __syncthreads();
    }

    // ---- epilogue ----
#pragma unroll
    for (int mb = 0; mb < 4; mb++) {
        int r0 = rowBase + wm * 64 + mb * 16 + (lane >> 2);
#pragma unroll
        for (int nb = 0; nb < 4; nb++) {
            int cc = colBase + wn * 32 + nb * 8 + (lane & 3) * 2;
            if (mode == 0) {
                uint32_t H, L;
                split_pair(acc[mb][nb][0] * scale, acc[mb][nb][1] * scale, H, L);
                *(uint32_t*)(Chi + (size_t)r0 * D_ + cc) = H;
                *(uint32_t*)(Clo + (size_t)r0 * D_ + cc) = L;
                split_pair(acc[mb][nb][2] * scale, acc[mb][nb][3] * scale, H, L);
                *(uint32_t*)(Chi + (size_t)(r0 + 8) * D_ + cc) = H;
                *(uint32_t*)(Clo + (size_t)(r0 + 8) * D_ + cc) = L;
            } else {
                *(float2*)(outParam + (size_t)r0 * D_ + cc) =
                    make_float2(acc[mb][nb][0], acc[mb][nb][1]);
                *(float2*)(outParam + (size_t)(r0 + 8) * D_ + cc) =
                    make_float2(acc[mb][nb][2], acc[mb][nb][3]);
            }
        }
    }
}

// ---------------------------------------------------------------------------
// Flash attention (causal) on tensor cores. Block = 128 q-rows of one (b,h),
// 8 warps x 16 rows. K-tiles of 64, double-buffered cp.async.
// S = Qhi*Khi + Qhi*Klo + Qlo*Khi ; PV = Phi*Vhi + Phi*Vlo + Plo*Vhi.
// P stays in registers (S accumulator fragments -> A fragments).
// ---------------------------------------------------------------------------
#define AT_STRIDE 144               // 64 bf16 = 128B data + 16B pad
#define AT_SPLIT  (64*AT_STRIDE)    // 9216 per matrix per split
#define AT_STAGE  (4*AT_SPLIT)      // Khi,Klo,Vhi,Vlo = 36864
#define AT_SMEM   (2*AT_STAGE)      // 73728
#define QSPLIT    (128*AT_STRIDE)   // 18432 (Q tile per split, prologue only)

__global__ __launch_bounds__(256) void attn_kernel()
{
    extern __shared__ char sm[];
    const uint32_t sb = smem_u32(sm);
    const int tid  = threadIdx.x;
    const int w    = tid >> 5;
    const int lane = tid & 31;

    const int qt = (int)gridDim.x - 1 - (int)blockIdx.x;  // heavy blocks first
    const int h  = blockIdx.y;
    const int b  = blockIdx.z;
    const int qB = qt * 128;
    const size_t bhBase = (size_t)(b * T_) * D_ + h * 64;

    // ---- prologue: Q tile (hi/lo) -> stage0 smem -> register fragments ----
    {
#pragma unroll
        for (int i = 0; i < 8; i++) {
            int c = tid + i * 256;
            int split = c >> 10, rem = c & 1023;
            int r = rem >> 3, ch = rem & 7;
            const __nv_bfloat16* src = (split ? g_Qlo : g_Qhi)
                + bhBase + (size_t)(qB + r) * D_ + ch * 8;
            CP_ASYNC16(sb + split * QSPLIT + r * AT_STRIDE + ch * 16, src);
        }
        CP_COMMIT();
        CP_WAIT(0);
    }
    __syncthreads();

    uint32_t qh[4][4], ql[4][4];
#pragma unroll
    for (int kc = 0; kc < 4; kc++) {
        uint32_t a = sb + (uint32_t)(w * 16 + (lane & 15)) * AT_STRIDE
                   + kc * 32 + (lane >> 4) * 16;
        ldsm4(qh[kc], a);
        ldsm4(ql[kc], a + QSPLIT);
    }
    __syncthreads();   // Q consumed; stage0 reusable

    // ---- K/V stage loader ----
    auto load_kv = [&](int kt, int st) {
        uint32_t s0 = sb + st * AT_STAGE;
        int kB = kt * 64;
#pragma unroll
        for (int i = 0; i < 8; i++) {
            int c = tid + i * 256;
            int arr = c >> 9, rem = c & 511;
            int r = rem >> 3, ch = rem & 7;
            const __nv_bfloat16* src =
                (arr == 0 ? g_Khi : arr == 1 ? g_Klo : arr == 2 ? g_Vhi : g_Vlo)
                + bhBase + (size_t)(kB + r) * D_ + ch * 8;
            CP_ASYNC16(s0 + arr * AT_SPLIT + r * AT_STRIDE + ch * 16, src);
        }
    };

    float sO[8][4];
#pragma unroll
    for (int nb = 0; nb < 8; nb++)
#pragma unroll
        for (int e = 0; e < 4; e++) sO[nb][e] = 0.0f;
    float m0 = -INFINITY, m1 = -INFINITY, l0 = 0.0f, l1 = 0.0f;

    const int nk = 2 * qt + 2;
    load_kv(0, 0);
    CP_COMMIT();

    for (int kt = 0; kt < nk; kt++) {
        const int st = kt & 1;
        if (kt + 1 < nk) {
            load_kv(kt + 1, st ^ 1);
            CP_COMMIT();
            CP_WAIT(1);
        } else {
            CP_WAIT(0);
        }
        __syncthreads();

        const uint32_t pK = sb + st * AT_STAGE;
        const uint32_t pV = pK + 2 * AT_SPLIT;
        const int g  = lane >> 3;
        const int l7 = lane & 7;

        // ---- S = Q K^T (3-pass split) ----
        float sS[8][4];
#pragma unroll
        for (int nb = 0; nb < 8; nb++)
#pragma unroll
            for (int e = 0; e < 4; e++) sS[nb][e] = 0.0f;

#pragma unroll
        for (int kc = 0; kc < 4; kc++)
#pragma unroll
            for (int np = 0; np < 4; np++) {
                uint32_t kh[4], kl[4];
                uint32_t ka = pK + (uint32_t)(np * 16 + (g >> 1) * 8 + l7) * AT_STRIDE
                            + kc * 32 + (g & 1) * 16;
                ldsm4(kh, ka);
                ldsm4(kl, ka + AT_SPLIT);
                mma_bf16(sS[2*np],   qh[kc], kh);
                mma_bf16(sS[2*np],   qh[kc], kl);
                mma_bf16(sS[2*np],   ql[kc], kh);
                mma_bf16(sS[2*np+1], qh[kc], kh + 2);
                mma_bf16(sS[2*np+1], qh[kc], kl + 2);
                mma_bf16(sS[2*np+1], ql[kc], kh + 2);
            }

        // ---- causal mask (only on the two diagonal-overlap tiles) ----
        if (kt >= 2 * qt) {
            const int kB = kt * 64;
            const int r0 = qB + w * 16 + (lane >> 2);
#pragma unroll
            for (int nb = 0; nb < 8; nb++) {
                int cb = kB + nb * 8 + (lane & 3) * 2;
                if (cb     > r0)     sS[nb][0] = -INFINITY;
                if (cb + 1 > r0)     sS[nb][1] = -INFINITY;
                if (cb     > r0 + 8) sS[nb][2] = -INFINITY;
                if (cb + 1 > r0 + 8) sS[nb][3] = -INFINITY;
            }
        }

        // ---- online softmax (rows r0 = lane/4, r1 = r0+8 within warp tile) ----
        float mt0 = -INFINITY, mt1 = -INFINITY;
#pragma unroll
        for (int nb = 0; nb < 8; nb++) {
            mt0 = fmaxf(mt0, fmaxf(sS[nb][0], sS[nb][1]));
            mt1 = fmaxf(mt1, fmaxf(sS[nb][2], sS[nb][3]));
        }
        mt0 = fmaxf(mt0, __shfl_xor_sync(0xffffffffu, mt0, 1));
        mt0 = fmaxf(mt0, __shfl_xor_sync(0xffffffffu, mt0, 2));
        mt1 = fmaxf(mt1, __shfl_xor_sync(0xffffffffu, mt1, 1));
        mt1 = fmaxf(mt1, __shfl_xor_sync(0xffffffffu, mt1, 2));

        float mn0 = fmaxf(m0, mt0), mn1 = fmaxf(m1, mt1);
        float c0 = __expf(m0 - mn0), c1 = __expf(m1 - mn1);
        float rs0 = 0.0f, rs1 = 0.0f;
#pragma unroll
        for (int nb = 0; nb < 8; nb++) {
            sS[nb][0] = __expf(sS[nb][0] - mn0);
            sS[nb][1] = __expf(sS[nb][1] - mn0);
            sS[nb][2] = __expf(sS[nb][2] - mn1);
            sS[nb][3] = __expf(sS[nb][3] - mn1);
            rs0 += sS[nb][0] + sS[nb][1];
            rs1 += sS[nb][2] + sS[nb][3];
        }
        rs0 += __shfl_xor_sync(0xffffffffu, rs0, 1);
        rs0 += __shfl_xor_sync(0xffffffffu, rs0, 2);
        rs1 += __shfl_xor_sync(0xffffffffu, rs1, 1);
        rs1 += __shfl_xor_sync(0xffffffffu, rs1, 2);
        l0 = l0 * c0 + rs0;  m0 = mn0;
        l1 = l1 * c1 + rs1;  m1 = mn1;
#pragma unroll
        for (int nb = 0; nb < 8; nb++) {
            sO[nb][0] *= c0; sO[nb][1] *= c0;
            sO[nb][2] *= c1; sO[nb][3] *= c1;
        }

        // ---- O += P V (3-pass split; P from registers) ----
#pragma unroll
        for (int kc = 0; kc < 4; kc++) {
            uint32_t ph[4], pl[4];
            split_pair(sS[2*kc][0],   sS[2*kc][1],   ph[0], pl[0]);
            split_pair(sS[2*kc][2],   sS[2*kc][3],   ph[1], pl[1]);
            split_pair(sS[2*kc+1][0], sS[2*kc+1][1], ph[2], pl[2]);
            split_pair(sS[2*kc+1][2], sS[2*kc+1][3], ph[3], pl[3]);
#pragma unroll
            for (int np = 0; np < 4; np++) {
                uint32_t vh[4], vl[4];
                uint32_t va = pV + (uint32_t)(kc * 16 + (g & 1) * 8 + l7) * AT_STRIDE
                            + np * 32 + (g >> 1) * 16;
                ldsm4t(vh, va);
                ldsm4t(vl, va + AT_SPLIT);
                mma_bf16(sO[2*np],   ph, vh);
                mma_bf16(sO[2*np],   ph, vl);
                mma_bf16(sO[2*np],   pl, vh);
                mma_bf16(sO[2*np+1], ph, vh + 2);
                mma_bf16(sO[2*np+1], ph, vl + 2);
                mma_bf16(sO[2*np+1], pl, vh + 2);
            }
        }
        __syncthreads();
    }

    // ---- epilogue: normalize, split to bf16 hi/lo ctx ----
    const float i0 = 1.0f / l0, i1 = 1.0f / l1;
    const size_t base0 = bhBase + (size_t)(qB + w * 16 + (lane >> 2)) * D_
                       + (lane & 3) * 2;
#pragma unroll
    for (int nb = 0; nb < 8; nb++) {
        uint32_t H, L;
        split_pair(sO[nb][0] * i0, sO[nb][1] * i0, H, L);
        *(uint32_t*)(g_Chi + base0 + nb * 8) = H;
        *(uint32_t*)(g_Clo + base0 + nb * 8) = L;
        split_pair(sO[nb][2] * i1, sO[nb][3] * i1, H, L);
        *(uint32_t*)(g_Chi + base0 + (size_t)8 * D_ + nb * 8) = H;
        *(uint32_t*)(g_Clo + base0 + (size_t)8 * D_ + nb * 8) = L;
    }
}

// ---------------------------------------------------------------------------

extern "C" void kernel_launch(void* const* d_in, const int* in_sizes, int n_in,
                              void* d_out, int out_size)
{
    const float* x  = (const float*)d_in[0];
    const float* Wq = (const float*)d_in[1];
    const float* Wk = (const float*)d_in[2];
    const float* Wv = (const float*)d_in[3];
    const float* Wo = (const float*)d_in[4];
    float* out = (float*)d_out;

    cudaFuncSetAttribute(gemm_kernel, cudaFuncAttributeMaxDynamicSharedMemorySize,
                         GEMM_SMEM);
    cudaFuncSetAttribute(attn_kernel, cudaFuncAttributeMaxDynamicSharedMemorySize,
                         AT_SMEM);

    // Split x into bf16 hi/lo; transpose+split all 4 weight matrices
    split_kernel<<<RTOT * D_ / 1024, 256>>>(x);
    wtrans_kernel<<<dim3(32, 32, 4), dim3(32, 8)>>>(Wq, Wk, Wv, Wo);

    // QKV projections on tensor cores -> bf16 hi/lo (Q pre-scaled 1/8)
    gemm_kernel<<<dim3(D_ / 128, RTOT / 128, 3), 256, GEMM_SMEM>>>(0, nullptr);

    // Causal flash attention on tensor cores -> ctx bf16 hi/lo
    attn_kernel<<<dim3(T_ / 128, NH_, B_), 256, AT_SMEM>>>();

    // Output projection on tensor cores -> fp32 out
    gemm_kernel<<<dim3(D_ / 128, RTOT / 128, 1), 256, GEMM_SMEM>>>(1, out);
}